// round 10
// baseline (speedup 1.0000x reference)
#include <cuda_runtime.h>
#include <cuda_bf16.h>
#include <math.h>

#define BINS  10
#define BLOCK 256
#define MAXB  5              // 5 blocks/SM -> 51-reg budget, 40 warps/SM
#define GRID  (148 * MAXB)   // 740, one full wave

// Per-block partials, bin-major for coalesced last-block reads.
// Written unconditionally by every block every launch -> no zeroing needed.
__device__ float g_psum[BINS * GRID];
__device__ float g_pcnt[BINS * GRID];
__device__ unsigned int g_ticket;   // zero-init at load; last block resets each launch

__device__ __forceinline__ void process_elem(float p, float t, float w,
                                             float2* __restrict__ hist) {
    if (w > 0.0f) {
        float ap = fabsf(p);
        float e  = __expf(-ap);                 // exp(-|p|)
        float r;                                 // approx 1/(1+e): binning only
        asm("rcp.approx.f32 %0, %1;" : "=f"(r) : "f"(1.0f + e));
        float s  = (p >= 0.0f) ? r : e * r;     // sigmoid(p)
        float g  = fabsf(s - t);
        int bin  = (int)(g * 10.0f);
        bin = bin > (BINS - 1) ? (BINS - 1) : bin;
        // bce independent of the approx recip:
        float bce = fmaxf(p, 0.0f) - p * t + __logf(1.0f + e);
        float2 a = hist[bin * BLOCK];           // LDS.64, conflict-free
        a.x += bce;
        a.y += 1.0f;
        hist[bin * BLOCK] = a;                  // STS.64
    }
}

__global__ void __launch_bounds__(BLOCK, MAXB)
ghm_main(const float* __restrict__ pred,
         const float* __restrict__ target,
         const float* __restrict__ lw,
         int n, float* __restrict__ out) {
    // Dual per-thread histogram banks: consecutive elements alternate banks,
    // halving the same-bin LDS->FADD->STS serial chain. [bin][tid] layout
    // keeps 64-bit accesses conflict-free.
    __shared__ float2 s_histA[BINS * BLOCK];
    __shared__ float2 s_histB[BINS * BLOCK];

    const int tid = threadIdx.x;
    float2* __restrict__ hA = s_histA + tid;
    float2* __restrict__ hB = s_histB + tid;
#pragma unroll
    for (int b = 0; b < BINS; b++) {
        hA[b * BLOCK] = make_float2(0.0f, 0.0f);
        hB[b * BLOCK] = make_float2(0.0f, 0.0f);
    }

    const int n4 = n >> 2;
    const float4* __restrict__ p4 = (const float4*)pred;
    const float4* __restrict__ t4 = (const float4*)target;
    const float4* __restrict__ w4 = (const float4*)lw;

    const int stride = GRID * BLOCK;
    int i = blockIdx.x * BLOCK + tid;

    if (i < n4) {
        // Depth-1 register pipeline (materializes under the MAXB=5 reg budget).
        float4 pa = p4[i];
        float4 ta = t4[i];
        float4 wa = w4[i];
        int inext = i + stride;
        while (inext < n4) {
            float4 pb = p4[inext];
            float4 tb = t4[inext];
            float4 wb = w4[inext];
            process_elem(pa.x, ta.x, wa.x, hA);
            process_elem(pa.y, ta.y, wa.y, hB);
            process_elem(pa.z, ta.z, wa.z, hA);
            process_elem(pa.w, ta.w, wa.w, hB);
            pa = pb; ta = tb; wa = wb;
            inext += stride;
        }
        process_elem(pa.x, ta.x, wa.x, hA);
        process_elem(pa.y, ta.y, wa.y, hB);
        process_elem(pa.z, ta.z, wa.z, hA);
        process_elem(pa.w, ta.w, wa.w, hB);
    }
    // Scalar tail (n not multiple of 4) — block 0 only.
    if (blockIdx.x == 0) {
        for (int j = (n4 << 2) + tid; j < n; j += BLOCK)
            process_elem(pred[j], target[j], lw[j], hA);
    }

    __syncthreads();
    // Merge bank B into bank A, then tree-reduce.
    {
#pragma unroll
        for (int b = 0; b < BINS; b++) {
            float2 x = s_histA[b * BLOCK + tid];
            float2 y = s_histB[b * BLOCK + tid];
            s_histA[b * BLOCK + tid] = make_float2(x.x + y.x, x.y + y.y);
        }
    }
    __syncthreads();
    for (int s = BLOCK / 2; s > 0; s >>= 1) {
        if (tid < s) {
#pragma unroll
            for (int b = 0; b < BINS; b++) {
                float2 x = s_histA[b * BLOCK + tid];
                float2 y = s_histA[b * BLOCK + tid + s];
                s_histA[b * BLOCK + tid] = make_float2(x.x + y.x, x.y + y.y);
            }
        }
        __syncthreads();
    }
    if (tid < BINS) {
        float2 v = s_histA[tid * BLOCK];
        g_psum[tid * GRID + blockIdx.x] = v.x;
        g_pcnt[tid * GRID + blockIdx.x] = v.y;   // <= ~45K, fp32-exact integer
        __threadfence();   // release, writers only
    }
    __syncthreads();

    // ---- last-block finalization (no extra kernel launches) ----
    __shared__ bool s_last;
    if (tid == 0) {
        unsigned int t = atomicAdd(&g_ticket, 1u);
        s_last = (t == GRID - 1u);
    }
    __syncthreads();
    if (!s_last) return;

    // Reuse bank-B smem for the cross-warp double partials.
    const int NW = BLOCK / 32;
    double* r_sum = (double*)s_histB;
    double* r_cnt = r_sum + BINS * NW;
    const int lane = tid & 31, wid = tid >> 5;

#pragma unroll
    for (int b = 0; b < BINS; b++) {
        float fs = 0.0f, fc = 0.0f;
        const float4* srow = (const float4*)&g_psum[b * GRID];
        const float4* crow = (const float4*)&g_pcnt[b * GRID];
        for (int j = tid; j < GRID / 4; j += BLOCK) {
            float4 vs = __ldcg(&srow[j]);   // coalesced, bypass stale L1
            float4 vc = __ldcg(&crow[j]);
            fs += (vs.x + vs.y) + (vs.z + vs.w);
            fc += (vc.x + vc.y) + (vc.z + vc.w);  // sums of small exact ints
        }
        double ds = (double)fs, dc = (double)fc;
#pragma unroll
        for (int o = 16; o > 0; o >>= 1) {
            ds += __shfl_down_sync(0xFFFFFFFFu, ds, o);
            dc += __shfl_down_sync(0xFFFFFFFFu, dc, o);
        }
        if (lane == 0) { r_sum[b * NW + wid] = ds; r_cnt[b * NW + wid] = dc; }
    }
    __syncthreads();

    if (tid == 0) {
        double acc = 0.0;
        int ne = 0;
#pragma unroll
        for (int b = 0; b < BINS; b++) {
            double s = 0.0, c = 0.0;
#pragma unroll
            for (int w = 0; w < NW; w++) { s += r_sum[b * NW + w]; c += r_cnt[b * NW + w]; }
            if (c > 0.0) { acc += s / c; ne++; }
        }
        float loss = (ne > 0) ? (float)(acc / (double)ne) : 0.0f;
        out[0] = loss * 1.0f;   // LOSS_WEIGHT
        g_ticket = 0u;          // reset for next graph replay
    }
}

extern "C" void kernel_launch(void* const* d_in, const int* in_sizes, int n_in,
                              void* d_out, int out_size) {
    const float* pred   = (const float*)d_in[0];
    const float* target = (const float*)d_in[1];
    const float* lw     = (const float*)d_in[2];
    float* out = (float*)d_out;
    int n = in_sizes[0];

    ghm_main<<<GRID, BLOCK>>>(pred, target, lw, n, out);
}

// round 11
// speedup vs baseline: 1.1128x; 1.1128x over previous
#include <cuda_runtime.h>
#include <cuda_bf16.h>
#include <math.h>

#define BINS 10
#define BLOCK 256
#define GRID  1184   // 148 SMs * 8 (grid-stride; also fine on 152-SM parts)

// Global scratch (no allocations allowed) — zeroed by ghm_zero each launch.
__device__ double       g_sum[BINS];
__device__ unsigned int g_cnt[BINS];

__global__ void ghm_zero() {
    int t = threadIdx.x;
    if (t < BINS) { g_sum[t] = 0.0; g_cnt[t] = 0u; }
}

__device__ __forceinline__ void process_elem(float p, float t, float w,
                                             float* s_sum, float* s_cnt, int tid) {
    if (w > 0.0f) {
        float ap = fabsf(p);
        float e  = __expf(-ap);          // exp(-|p|), shared by sigmoid and log1p term
        float r  = __frcp_rn(1.0f + e);  // 1/(1+e)
        float s  = (p >= 0.0f) ? r : e * r;   // sigmoid(p)
        float g  = fabsf(s - t);
        int bin  = (int)(g * 10.0f);
        bin = bin > (BINS - 1) ? (BINS - 1) : bin;
        // bce = max(p,0) - p*t + log1p(exp(-|p|)); log(1+e) is accurate enough (e<=1)
        float bce = fmaxf(p, 0.0f) - p * t + __logf(1.0f + e);
        s_sum[bin * BLOCK + tid] += bce;
        s_cnt[bin * BLOCK + tid] += 1.0f;
    }
}

__global__ void __launch_bounds__(BLOCK)
ghm_main(const float* __restrict__ pred,
         const float* __restrict__ target,
         const float* __restrict__ lw,
         int n) {
    // Per-thread private histogram columns: [bin][tid] -> bank = tid%32, conflict-free.
    __shared__ float s_sum[BINS * BLOCK];
    __shared__ float s_cnt[BINS * BLOCK];

    const int tid = threadIdx.x;
#pragma unroll
    for (int b = 0; b < BINS; b++) {
        s_sum[b * BLOCK + tid] = 0.0f;
        s_cnt[b * BLOCK + tid] = 0.0f;
    }

    const int n4 = n >> 2;
    const float4* __restrict__ p4 = (const float4*)pred;
    const float4* __restrict__ t4 = (const float4*)target;
    const float4* __restrict__ w4 = (const float4*)lw;

    const int stride = gridDim.x * BLOCK;
    for (int i = blockIdx.x * BLOCK + tid; i < n4; i += stride) {
        float4 p = p4[i];
        float4 t = t4[i];
        float4 w = w4[i];
        process_elem(p.x, t.x, w.x, s_sum, s_cnt, tid);
        process_elem(p.y, t.y, w.y, s_sum, s_cnt, tid);
        process_elem(p.z, t.z, w.z, s_sum, s_cnt, tid);
        process_elem(p.w, t.w, w.w, s_sum, s_cnt, tid);
    }
    // Scalar tail (n not multiple of 4) — block 0 only.
    if (blockIdx.x == 0) {
        for (int i = (n4 << 2) + tid; i < n; i += BLOCK)
            process_elem(pred[i], target[i], lw[i], s_sum, s_cnt, tid);
    }

    __syncthreads();
    // Tree-reduce each bin's 256 partials.
    for (int s = BLOCK / 2; s > 0; s >>= 1) {
        if (tid < s) {
#pragma unroll
            for (int b = 0; b < BINS; b++) {
                s_sum[b * BLOCK + tid] += s_sum[b * BLOCK + tid + s];
                s_cnt[b * BLOCK + tid] += s_cnt[b * BLOCK + tid + s];
            }
        }
        __syncthreads();
    }
    if (tid < BINS) {
        atomicAdd(&g_sum[tid], (double)s_sum[tid * BLOCK]);
        atomicAdd(&g_cnt[tid], (unsigned int)s_cnt[tid * BLOCK]);
    }
}

__global__ void ghm_final(float* __restrict__ out) {
    if (threadIdx.x == 0) {
        double acc = 0.0;
        int ne = 0;
#pragma unroll
        for (int b = 0; b < BINS; b++) {
            unsigned int c = g_cnt[b];
            if (c > 0u) { acc += g_sum[b] / (double)c; ne++; }
        }
        float loss = (ne > 0) ? (float)(acc / (double)ne) : 0.0f;
        out[0] = loss * 1.0f;  // LOSS_WEIGHT
    }
}

extern "C" void kernel_launch(void* const* d_in, const int* in_sizes, int n_in,
                              void* d_out, int out_size) {
    const float* pred   = (const float*)d_in[0];
    const float* target = (const float*)d_in[1];
    const float* lw     = (const float*)d_in[2];
    float* out = (float*)d_out;
    int n = in_sizes[0];

    ghm_zero<<<1, 32>>>();
    ghm_main<<<GRID, BLOCK>>>(pred, target, lw, n);
    ghm_final<<<1, 32>>>(out);
}

// round 12
// speedup vs baseline: 1.1446x; 1.0286x over previous
#include <cuda_runtime.h>
#include <cuda_bf16.h>
#include <math.h>

#define BINS 10
#define BLOCK 256
#define GRID  1184   // 148 SMs * 8 (grid-stride; also fine on 152-SM parts)

// Global scratch (no allocations allowed).
// Zero at module load; ghm_final re-zeroes after each use -> every launch
// (first call, capture, and every graph replay) starts from zeroed state.
__device__ double       g_sum[BINS];
__device__ unsigned int g_cnt[BINS];

__device__ __forceinline__ void process_elem(float p, float t, float w,
                                             float* s_sum, float* s_cnt, int tid) {
    if (w > 0.0f) {
        float ap = fabsf(p);
        float e  = __expf(-ap);          // exp(-|p|), shared by sigmoid and log1p term
        float r  = __frcp_rn(1.0f + e);  // 1/(1+e)
        float s  = (p >= 0.0f) ? r : e * r;   // sigmoid(p)
        float g  = fabsf(s - t);
        int bin  = (int)(g * 10.0f);
        bin = bin > (BINS - 1) ? (BINS - 1) : bin;
        // bce = max(p,0) - p*t + log1p(exp(-|p|)); log(1+e) is accurate enough (e<=1)
        float bce = fmaxf(p, 0.0f) - p * t + __logf(1.0f + e);
        s_sum[bin * BLOCK + tid] += bce;
        s_cnt[bin * BLOCK + tid] += 1.0f;
    }
}

__global__ void __launch_bounds__(BLOCK)
ghm_main(const float* __restrict__ pred,
         const float* __restrict__ target,
         const float* __restrict__ lw,
         int n) {
    // Per-thread private histogram columns: [bin][tid] -> bank = tid%32, conflict-free.
    __shared__ float s_sum[BINS * BLOCK];
    __shared__ float s_cnt[BINS * BLOCK];

    const int tid = threadIdx.x;
#pragma unroll
    for (int b = 0; b < BINS; b++) {
        s_sum[b * BLOCK + tid] = 0.0f;
        s_cnt[b * BLOCK + tid] = 0.0f;
    }

    const int n4 = n >> 2;
    const float4* __restrict__ p4 = (const float4*)pred;
    const float4* __restrict__ t4 = (const float4*)target;
    const float4* __restrict__ w4 = (const float4*)lw;

    const int stride = gridDim.x * BLOCK;
    for (int i = blockIdx.x * BLOCK + tid; i < n4; i += stride) {
        float4 p = p4[i];
        float4 t = t4[i];
        float4 w = w4[i];
        process_elem(p.x, t.x, w.x, s_sum, s_cnt, tid);
        process_elem(p.y, t.y, w.y, s_sum, s_cnt, tid);
        process_elem(p.z, t.z, w.z, s_sum, s_cnt, tid);
        process_elem(p.w, t.w, w.w, s_sum, s_cnt, tid);
    }
    // Scalar tail (n not multiple of 4) — block 0 only.
    if (blockIdx.x == 0) {
        for (int i = (n4 << 2) + tid; i < n; i += BLOCK)
            process_elem(pred[i], target[i], lw[i], s_sum, s_cnt, tid);
    }

    __syncthreads();
    // Tree-reduce each bin's 256 partials.
    for (int s = BLOCK / 2; s > 0; s >>= 1) {
        if (tid < s) {
#pragma unroll
            for (int b = 0; b < BINS; b++) {
                s_sum[b * BLOCK + tid] += s_sum[b * BLOCK + tid + s];
                s_cnt[b * BLOCK + tid] += s_cnt[b * BLOCK + tid + s];
            }
        }
        __syncthreads();
    }
    if (tid < BINS) {
        atomicAdd(&g_sum[tid], (double)s_sum[tid * BLOCK]);
        atomicAdd(&g_cnt[tid], (unsigned int)s_cnt[tid * BLOCK]);
    }
}

__global__ void ghm_final(float* __restrict__ out) {
    if (threadIdx.x == 0) {
        double acc = 0.0;
        int ne = 0;
#pragma unroll
        for (int b = 0; b < BINS; b++) {
            unsigned int c = g_cnt[b];
            if (c > 0u) { acc += g_sum[b] / (double)c; ne++; }
        }
        float loss = (ne > 0) ? (float)(acc / (double)ne) : 0.0f;
        out[0] = loss * 1.0f;  // LOSS_WEIGHT

        // Self-clean for the next launch/replay (replaces the ghm_zero kernel).
#pragma unroll
        for (int b = 0; b < BINS; b++) {
            g_sum[b] = 0.0;
            g_cnt[b] = 0u;
        }
    }
}

extern "C" void kernel_launch(void* const* d_in, const int* in_sizes, int n_in,
                              void* d_out, int out_size) {
    const float* pred   = (const float*)d_in[0];
    const float* target = (const float*)d_in[1];
    const float* lw     = (const float*)d_in[2];
    float* out = (float*)d_out;
    int n = in_sizes[0];

    ghm_main<<<GRID, BLOCK>>>(pred, target, lw, n);
    ghm_final<<<1, 32>>>(out);
}